// round 16
// baseline (speedup 1.0000x reference)
#include <cuda_runtime.h>
#include <cuda_fp16.h>

// ---------------------------------------------------------------------------
// WeightedTP via warp-level mma.sync (HMMA, fp16 1-term):
//   tp = A[2048 x 68*272] @ Wsym[68*272 x 128],  A[n,(k,j)] = h[n,k]*c[n,j]
// A and B single fp16 planes (rel_err 3.06e-4 measured, stable).
// R16: R15 tp unchanged (legacy-HMMA pipe floor, rt~12). Epilogue split:
//      reduce_kernel streams the 17-way k-split sum at near-peak BW (~3us),
//      out_kernel now FMA-bound on a 1MB input (~10us vs 21us).
// ---------------------------------------------------------------------------

#define MAXN 2048
#define NK 65            // real k rows (64 hidden + bias)
#define NKP 68           // padded (3 zero rows)
#define NJ 272           // 17 chunks of 16
#define NJC 17
#define KSPLIT 17
#define KC 4             // k-chunks per split (uniform)

#define PATH_COEFF 0.04419417382415922f
#define CG110      0.57735026918962576f
#define LN_EPS     1e-5f

__device__ float g_hT[64 * MAXN];                     // [k][n]
__device__ uint2 g_bf[(size_t)NKP * NJC * 16 * 32];   // B frags (fp16) [k][jc][wt][lane]
__device__ float4 g_cf[(size_t)(MAXN/16) * NJC * 32 * 2]; // c frags [mt][jc][lane][2]
__device__ float g_tp[(size_t)KSPLIT * MAXN * 128];
__device__ float g_red[(size_t)MAXN * 128];           // summed splits

__device__ __forceinline__ float silu_f(float v) { return v / (1.0f + __expf(-v)); }

// pack fp32 pair into one f16x2 (a0 -> low half)
__device__ __forceinline__ unsigned cvt2h(float a0, float a1) {
    __half2 h = __floats2half2_rn(a0, a1);
    return *reinterpret_cast<unsigned*>(&h);
}

__device__ __forceinline__ void mma16816(float* d, const unsigned* a,
                                         unsigned b0, unsigned b1) {
    asm volatile(
        "mma.sync.aligned.m16n8k16.row.col.f32.f16.f16.f32 "
        "{%0,%1,%2,%3}, {%4,%5,%6,%7}, {%8,%9}, {%0,%1,%2,%3};"
        : "+f"(d[0]), "+f"(d[1]), "+f"(d[2]), "+f"(d[3])
        : "r"(a[0]), "r"(a[1]), "r"(a[2]), "r"(a[3]), "r"(b0), "r"(b1));
}

// ---------------------------------------------------------------------------
// Kernel 1: symmetrize + pack B fragments (single fp16 plane), smem-tiled.
// Block per (k, jc); pad planes (k >= NK) are zero.
// ---------------------------------------------------------------------------
__global__ __launch_bounds__(256) void bfrag_kernel(const float* __restrict__ w2,
                                                    const float* __restrict__ b2) {
    __shared__ float sym[16][129];
    int bid = blockIdx.x;
    int k  = bid / NJC;
    int jc = bid % NJC;
    int tid = threadIdx.x;
    const float* src = (k < 64) ? (w2 + (size_t)k * 65536) : b2;

    #pragma unroll
    for (int i = 0; i < 8; i++) {
        int e  = tid + 256 * i;
        int pj = e >> 7;
        int w  = e & 127;
        float val = 0.0f;
        if (k < NK) {
            int j = jc * 16 + pj;
            int p = j / 136, q = j % 136, u = 0;
            while (q >= 16 - u) { q -= 16 - u; u++; }
            int v = u + q;
            val = src[((p * 256 + u * 16 + v) << 7) + w];
            if (u != v) val += src[((p * 256 + v * 16 + u) << 7) + w];
        }
        sym[pj][w] = val;
    }
    __syncthreads();

    #pragma unroll
    for (int i = 0; i < 2; i++) {
        int s = tid + 256 * i;
        int wt = s >> 5;
        int lane = s & 31;
        int w = wt * 8 + (lane >> 2);
        int jl0 = (lane & 3) * 2;
        uint2 o;
        o.x = cvt2h(sym[jl0][w],     sym[jl0 + 1][w]);
        o.y = cvt2h(sym[jl0 + 8][w], sym[jl0 + 9][w]);
        g_bf[((size_t)(k * NJC + jc) * 16 + wt) * 32 + lane] = o;
    }
}

// ---------------------------------------------------------------------------
// Kernel 2: fused prep — 16 rows/block (warp per row):
// h -> g_hT (transposed), c -> smem -> A-fragment quads g_cf.
// ---------------------------------------------------------------------------
__global__ __launch_bounds__(512) void prep_kernel(const float* __restrict__ x,
                                                   const float* __restrict__ lng,
                                                   const float* __restrict__ lnb,
                                                   const float* __restrict__ w1,
                                                   int N) {
    __shared__ float xs[16][64];
    __shared__ float lns[16][16];
    __shared__ float cs[16 * NJ];
    int tid = threadIdx.x;
    int warp = tid >> 5;
    int lane = tid & 31;
    int mt = blockIdx.x;
    int n = mt * 16 + warp;

    xs[warp][lane]      = x[(size_t)n * 64 + lane];
    xs[warp][lane + 32] = x[(size_t)n * 64 + 32 + lane];
    __syncwarp();

    float f = (lane < 16) ? xs[warp][lane] : 0.0f;
    float s = f;
    #pragma unroll
    for (int o = 16; o; o >>= 1) s += __shfl_xor_sync(0xffffffffu, s, o);
    float mu = s * (1.0f / 16.0f);
    float d = (lane < 16) ? (f - mu) : 0.0f;
    float ss = d * d;
    #pragma unroll
    for (int o = 16; o; o >>= 1) ss += __shfl_xor_sync(0xffffffffu, ss, o);
    float rstd = rsqrtf(ss * (1.0f / 16.0f) + LN_EPS);
    if (lane < 16) lns[warp][lane] = d * rstd * lng[lane] + lnb[lane];
    __syncwarp();

    #pragma unroll
    for (int t = 0; t < 2; t++) {
        int j = lane + 32 * t;
        float acc = 0.0f;
        #pragma unroll
        for (int i = 0; i < 16; i++) acc += lns[warp][i] * w1[i * 64 + j];
        g_hT[(size_t)j * MAXN + n] = silu_f(acc);
    }

    for (int t = lane; t < NJ; t += 32) {
        int p = t / 136, q = t % 136, u = 0;
        while (q >= 16 - u) { q -= 16 - u; u++; }
        int v = u + q;
        float val;
        if (p == 0) {
            val = PATH_COEFF * xs[warp][u] * xs[warp][v];
        } else {
            const float* a = &xs[warp][16 + u * 3];
            const float* b = &xs[warp][16 + v * 3];
            val = PATH_COEFF * CG110 * (a[0] * b[0] + a[1] * b[1] + a[2] * b[2]);
        }
        cs[warp * NJ + t] = val;
    }
    __syncthreads();

    for (int t = tid; t < NJC * 32; t += 512) {
        int l = t & 31;
        int jc = t >> 5;
        int ra = l >> 2;
        int j0 = jc * 16 + (l & 3) * 2;
        const float* c0 = cs + ra * NJ;
        const float* c8 = c0 + 8 * NJ;
        float4 f0, f1;
        f0.x = c0[j0];     f0.y = c0[j0 + 1]; f0.z = c8[j0];     f0.w = c8[j0 + 1];
        f1.x = c0[j0 + 8]; f1.y = c0[j0 + 9]; f1.z = c8[j0 + 8]; f1.w = c8[j0 + 9];
        size_t o = ((size_t)(mt * NJC + jc) * 32 + l) * 2;
        g_cf[o] = f0;
        g_cf[o + 1] = f1;
    }
}

// ---------------------------------------------------------------------------
// Kernel 3: HMMA contraction, fp16 1-term. Grid (N/128, 17), 256 threads,
// 2 CTA/SM. Warp tile 32 rows x 64 cols (mw = warp>>1, nh = warp&1).
// B double-buffered in smem, LDG prefetch one chunk ahead.
// ---------------------------------------------------------------------------
__global__ __launch_bounds__(256, 2) void tp_kernel(int N) {
    __shared__ float h_sm[KC * 128];
    __shared__ uint2 sbuf[2][512];
    int tid = threadIdx.x;
    int warp = tid >> 5;
    int lane = tid & 31;
    int mblk = blockIdx.x;
    int base = mblk * 128;
    int split = blockIdx.y;
    int k0 = split * KC;

    for (int s = tid; s < KC * 128; s += 256) {
        int k = k0 + (s >> 7);
        float hv = 0.0f;
        if (k < 64)       hv = g_hT[(size_t)k * MAXN + base + (s & 127)];
        else if (k == 64) hv = 1.0f;
        h_sm[s] = hv;
    }
    {   // preload chunk 0 (kk=0, jc=0)
        size_t o0 = (size_t)(k0 * NJC) * 512;
        sbuf[0][tid]       = g_bf[o0 + tid];
        sbuf[0][tid + 256] = g_bf[o0 + tid + 256];
    }
    __syncthreads();

    int mw = warp >> 1;       // 0..3: 32-row slice
    int nh = warp & 1;        // 0..1: 64-col slice
    int ra = lane >> 2;
    int qb = lane & 3;

    float acc[2][8][4];
    #pragma unroll
    for (int a = 0; a < 2; a++)
        #pragma unroll
        for (int b = 0; b < 8; b++)
            #pragma unroll
            for (int cdx = 0; cdx < 4; cdx++) acc[a][b][cdx] = 0.0f;

    const int T = NJC * KC;   // 68 chunks
    int t = 0;
    for (int jc = 0; jc < NJC; jc++) {
        float4 cf[2][2];
        #pragma unroll
        for (int mtl = 0; mtl < 2; mtl++) {
            int mt = mblk * 8 + mw * 2 + mtl;
            size_t o = ((size_t)(mt * NJC + jc) * 32 + lane) * 2;
            cf[mtl][0] = g_cf[o];
            cf[mtl][1] = g_cf[o + 1];
        }
        #pragma unroll
        for (int kk = 0; kk < KC; kk++, t++) {
            int cur = t & 1, nxt = cur ^ 1;
            bool hn = (t + 1 < T);
            uint2 p0, p1;
            if (hn) {
                int kn = kk + 1, jn = jc;
                if (kn == KC) { kn = 0; jn = jc + 1; }
                size_t off = (size_t)((k0 + kn) * NJC + jn) * 512;
                p0 = g_bf[off + tid];
                p1 = g_bf[off + tid + 256];
            }
            // A fragments for 2 m-subtiles
            unsigned ah[2][4];
            #pragma unroll
            for (int mtl = 0; mtl < 2; mtl++) {
                int r = mw * 32 + mtl * 16 + ra;
                float h0 = h_sm[kk * 128 + r];
                float h1 = h_sm[kk * 128 + r + 8];
                ah[mtl][0] = cvt2h(h0 * cf[mtl][0].x, h0 * cf[mtl][0].y);
                ah[mtl][1] = cvt2h(h1 * cf[mtl][0].z, h1 * cf[mtl][0].w);
                ah[mtl][2] = cvt2h(h0 * cf[mtl][1].x, h0 * cf[mtl][1].y);
                ah[mtl][3] = cvt2h(h1 * cf[mtl][1].z, h1 * cf[mtl][1].w);
            }
            const uint2* bl = &sbuf[cur][nh * 256 + lane];
            #pragma unroll
            for (int wt = 0; wt < 8; wt++) {
                uint2 bb = bl[wt * 32];
                mma16816(acc[0][wt], ah[0], bb.x, bb.y);
                mma16816(acc[1][wt], ah[1], bb.x, bb.y);
            }
            if (hn) {
                sbuf[nxt][tid]       = p0;
                sbuf[nxt][tid + 256] = p1;
            }
            __syncthreads();
        }
    }

    // D layout: d0,d1 = (row ra, col 2qb,2qb+1); d2,d3 = row ra+8.
    #pragma unroll
    for (int mtl = 0; mtl < 2; mtl++) {
        int r0 = base + mw * 32 + mtl * 16 + ra;
        #pragma unroll
        for (int wt = 0; wt < 8; wt++) {
            int col = nh * 64 + wt * 8 + 2 * qb;
            float2* q0 = reinterpret_cast<float2*>(
                g_tp + ((size_t)split * N + r0) * 128 + col);
            float2* q1 = reinterpret_cast<float2*>(
                g_tp + ((size_t)split * N + r0 + 8) * 128 + col);
            *q0 = make_float2(acc[mtl][wt][0], acc[mtl][wt][1]);
            *q1 = make_float2(acc[mtl][wt][2], acc[mtl][wt][3]);
        }
    }
}

// ---------------------------------------------------------------------------
// Kernel 3b: reduce — sum the 17 k-split planes into g_red (streaming).
// One thread per float4; MLP=17 independent strided loads.
// ---------------------------------------------------------------------------
__global__ __launch_bounds__(256) void reduce_kernel(int N) {
    int idx = blockIdx.x * 256 + threadIdx.x;
    const float4* src = reinterpret_cast<const float4*>(g_tp);
    size_t stride = (size_t)N * 32;       // N*128/4 float4 per split
    float4 s = src[idx];
    #pragma unroll
    for (int sp = 1; sp < KSPLIT; sp++) {
        float4 v = src[(size_t)sp * stride + idx];
        s.x += v.x; s.y += v.y; s.z += v.z; s.w += v.w;
    }
    reinterpret_cast<float4*>(g_red)[idx] = s;
}

// ---------------------------------------------------------------------------
// Kernel 4: epilogue — LN(128), silu(@om_w1), @om_w2 + b, from g_red.
// 8 rows per 256-thread block, i-dim split 2-way.
// ---------------------------------------------------------------------------
__global__ __launch_bounds__(256) void out_kernel(const float* __restrict__ lng,
                                                  const float* __restrict__ lnb,
                                                  const float* __restrict__ w1,
                                                  const float* __restrict__ w2,
                                                  const float* __restrict__ bias2,
                                                  float* __restrict__ out, int N) {
    __shared__ float ln_sm[8][128];
    __shared__ float y_sm[8][512];
    __shared__ float part_sm[8][128];
    int tid = threadIdx.x, lane = tid & 31, warp = tid >> 5;
    int rowbase = blockIdx.x * 8;

    {
        int g = rowbase + warp;
        float v[4];
        #pragma unroll
        for (int t = 0; t < 4; t++)
            v[t] = g_red[(size_t)g * 128 + lane + 32 * t];
        float s = v[0] + v[1] + v[2] + v[3];
        #pragma unroll
        for (int o = 16; o; o >>= 1) s += __shfl_xor_sync(0xffffffffu, s, o);
        float mu = s * (1.0f / 128.0f);
        float ss = 0.0f;
        #pragma unroll
        for (int t = 0; t < 4; t++) { float d = v[t] - mu; ss += d * d; }
        #pragma unroll
        for (int o = 16; o; o >>= 1) ss += __shfl_xor_sync(0xffffffffu, ss, o);
        float rstd = rsqrtf(ss * (1.0f / 128.0f) + LN_EPS);
        #pragma unroll
        for (int t = 0; t < 4; t++) {
            int i = lane + 32 * t;
            ln_sm[warp][i] = (v[t] - mu) * rstd * lng[i] + lnb[i];
        }
    }
    __syncthreads();

    int q = tid & 127, hf = tid >> 7;
    float y[8][4];
    #pragma unroll
    for (int r = 0; r < 8; r++)
        #pragma unroll
        for (int cdx = 0; cdx < 4; cdx++) y[r][cdx] = 0.0f;

    const float4* w1v = reinterpret_cast<const float4*>(w1);
    #pragma unroll 8
    for (int ii = 0; ii < 64; ii++) {
        int i = hf * 64 + ii;
        float4 wv = w1v[i * 128 + q];
        #pragma unroll
        for (int r = 0; r < 8; r++) {
            float l = ln_sm[r][i];
            y[r][0] += l * wv.x;
            y[r][1] += l * wv.y;
            y[r][2] += l * wv.z;
            y[r][3] += l * wv.w;
        }
    }
    if (hf == 1) {
        #pragma unroll
        for (int r = 0; r < 8; r++) {
            y_sm[r][q * 4]     = y[r][0];
            y_sm[r][q * 4 + 1] = y[r][1];
            y_sm[r][q * 4 + 2] = y[r][2];
            y_sm[r][q * 4 + 3] = y[r][3];
        }
    }
    __syncthreads();

    if (hf == 0) {
        float4 w2v = reinterpret_cast<const float4*>(w2)[q];
        #pragma unroll
        for (int r = 0; r < 8; r++) {
            float a0 = y[r][0] + y_sm[r][q * 4];
            float a1 = y[r][1] + y_sm[r][q * 4 + 1];
            float a2 = y[r][2] + y_sm[r][q * 4 + 2];
            float a3 = y[r][3] + y_sm[r][q * 4 + 3];
            part_sm[r][q] = silu_f(a0) * w2v.x + silu_f(a1) * w2v.y +
                            silu_f(a2) * w2v.z + silu_f(a3) * w2v.w;
        }
    }
    __syncthreads();

    {
        float s = part_sm[warp][lane] + part_sm[warp][lane + 32] +
                  part_sm[warp][lane + 64] + part_sm[warp][lane + 96];
        #pragma unroll
        for (int o = 16; o; o >>= 1) s += __shfl_xor_sync(0xffffffffu, s, o);
        if (lane == 0) out[rowbase + warp] = s + bias2[0];
    }
}

// ---------------------------------------------------------------------------
extern "C" void kernel_launch(void* const* d_in, const int* in_sizes, int n_in,
                              void* d_out, int out_size) {
    const float* x        = (const float*)d_in[0];
    const float* we_ln_g  = (const float*)d_in[1];
    const float* we_ln_b  = (const float*)d_in[2];
    const float* we_w1    = (const float*)d_in[3];
    const float* we_w2    = (const float*)d_in[4];
    const float* we_b2    = (const float*)d_in[5];
    const float* om_ln_g  = (const float*)d_in[6];
    const float* om_ln_b  = (const float*)d_in[7];
    const float* om_w1    = (const float*)d_in[8];
    const float* om_w2    = (const float*)d_in[9];
    const float* om_b2    = (const float*)d_in[10];

    int N = in_sizes[0] / 64;
    if (N > MAXN) N = MAXN;

    bfrag_kernel<<<NKP * NJC, 256>>>(we_w2, we_b2);
    prep_kernel<<<N / 16, 512>>>(x, we_ln_g, we_ln_b, we_w1, N);
    tp_kernel<<<dim3(N / 128, KSPLIT), 256>>>(N);
    reduce_kernel<<<N * 32 / 256, 256>>>(N);
    out_kernel<<<N / 8, 256>>>(om_ln_g, om_ln_b, om_w1, om_w2, om_b2,
                               (float*)d_out, N);
}

// round 17
// speedup vs baseline: 1.0434x; 1.0434x over previous
#include <cuda_runtime.h>
#include <cuda_fp16.h>

// ---------------------------------------------------------------------------
// WeightedTP via warp-level mma.sync (HMMA, fp16 1-term):
//   tp = A[2048 x 68*272] @ Wsym[68*272 x 128],  A[n,(k,j)] = h[n,k]*c[n,j]
// R17: R15 tp unchanged (~85% of legacy-HMMA roofline, rt~16).
//      out_kernel phase B (LN @ om_w1, 134M MACs) moved to HMMA with
//      pre-packed om_w1 fragments; silu+w2 via shuffle reduce.
// ---------------------------------------------------------------------------

#define MAXN 2048
#define NK 65            // real k rows (64 hidden + bias)
#define NKP 68           // padded (3 zero rows)
#define NJ 272           // 17 chunks of 16
#define NJC 17
#define KSPLIT 17
#define KC 4             // k-chunks per split (uniform)

#define PATH_COEFF 0.04419417382415922f
#define CG110      0.57735026918962576f
#define LN_EPS     1e-5f

__device__ float g_hT[64 * MAXN];                     // [k][n]
__device__ uint2 g_bf[(size_t)NKP * NJC * 16 * 32];   // B frags (fp16) [k][jc][wt][lane]
__device__ float4 g_cf[(size_t)(MAXN/16) * NJC * 32 * 2]; // c frags [mt][jc][lane][2]
__device__ float g_tp[(size_t)KSPLIT * MAXN * 128];
__device__ uint2 g_w1f[8 * 64 * 32];                  // om_w1 frags [ks][wt][lane]

__device__ __forceinline__ float silu_f(float v) { return v / (1.0f + __expf(-v)); }

// pack fp32 pair into one f16x2 (a0 -> low half)
__device__ __forceinline__ unsigned cvt2h(float a0, float a1) {
    __half2 h = __floats2half2_rn(a0, a1);
    return *reinterpret_cast<unsigned*>(&h);
}

__device__ __forceinline__ void mma16816(float* d, const unsigned* a,
                                         unsigned b0, unsigned b1) {
    asm volatile(
        "mma.sync.aligned.m16n8k16.row.col.f32.f16.f16.f32 "
        "{%0,%1,%2,%3}, {%4,%5,%6,%7}, {%8,%9}, {%0,%1,%2,%3};"
        : "+f"(d[0]), "+f"(d[1]), "+f"(d[2]), "+f"(d[3])
        : "r"(a[0]), "r"(a[1]), "r"(a[2]), "r"(a[3]), "r"(b0), "r"(b1));
}

// ---------------------------------------------------------------------------
// Kernel 1: symmetrize + pack B fragments (single fp16 plane), smem-tiled.
// ---------------------------------------------------------------------------
__global__ __launch_bounds__(256) void bfrag_kernel(const float* __restrict__ w2,
                                                    const float* __restrict__ b2) {
    __shared__ float sym[16][129];
    int bid = blockIdx.x;
    int k  = bid / NJC;
    int jc = bid % NJC;
    int tid = threadIdx.x;
    const float* src = (k < 64) ? (w2 + (size_t)k * 65536) : b2;

    #pragma unroll
    for (int i = 0; i < 8; i++) {
        int e  = tid + 256 * i;
        int pj = e >> 7;
        int w  = e & 127;
        float val = 0.0f;
        if (k < NK) {
            int j = jc * 16 + pj;
            int p = j / 136, q = j % 136, u = 0;
            while (q >= 16 - u) { q -= 16 - u; u++; }
            int v = u + q;
            val = src[((p * 256 + u * 16 + v) << 7) + w];
            if (u != v) val += src[((p * 256 + v * 16 + u) << 7) + w];
        }
        sym[pj][w] = val;
    }
    __syncthreads();

    #pragma unroll
    for (int i = 0; i < 2; i++) {
        int s = tid + 256 * i;
        int wt = s >> 5;
        int lane = s & 31;
        int w = wt * 8 + (lane >> 2);
        int jl0 = (lane & 3) * 2;
        uint2 o;
        o.x = cvt2h(sym[jl0][w],     sym[jl0 + 1][w]);
        o.y = cvt2h(sym[jl0 + 8][w], sym[jl0 + 9][w]);
        g_bf[((size_t)(k * NJC + jc) * 16 + wt) * 32 + lane] = o;
    }
}

// ---------------------------------------------------------------------------
// Kernel 1b: pack om_w1 (128 x 512) into fp16 B-fragments [ks][wt][lane].
// ---------------------------------------------------------------------------
__global__ void w1frag_kernel(const float* __restrict__ w1) {
    int idx = blockIdx.x * 256 + threadIdx.x;
    if (idx >= 8 * 64 * 32) return;
    int lane = idx & 31;
    int wt   = (idx >> 5) & 63;
    int ks   = idx >> 11;
    int w  = wt * 8 + (lane >> 2);
    int k0 = ks * 16 + (lane & 3) * 2;
    uint2 o;
    o.x = cvt2h(w1[(size_t)k0 * 512 + w],       w1[(size_t)(k0 + 1) * 512 + w]);
    o.y = cvt2h(w1[(size_t)(k0 + 8) * 512 + w], w1[(size_t)(k0 + 9) * 512 + w]);
    g_w1f[idx] = o;
}

// ---------------------------------------------------------------------------
// Kernel 2: fused prep — 16 rows/block (warp per row):
// h -> g_hT (transposed), c -> smem -> A-fragment quads g_cf.
// ---------------------------------------------------------------------------
__global__ __launch_bounds__(512) void prep_kernel(const float* __restrict__ x,
                                                   const float* __restrict__ lng,
                                                   const float* __restrict__ lnb,
                                                   const float* __restrict__ w1,
                                                   int N) {
    __shared__ float xs[16][64];
    __shared__ float lns[16][16];
    __shared__ float cs[16 * NJ];
    int tid = threadIdx.x;
    int warp = tid >> 5;
    int lane = tid & 31;
    int mt = blockIdx.x;
    int n = mt * 16 + warp;

    xs[warp][lane]      = x[(size_t)n * 64 + lane];
    xs[warp][lane + 32] = x[(size_t)n * 64 + 32 + lane];
    __syncwarp();

    float f = (lane < 16) ? xs[warp][lane] : 0.0f;
    float s = f;
    #pragma unroll
    for (int o = 16; o; o >>= 1) s += __shfl_xor_sync(0xffffffffu, s, o);
    float mu = s * (1.0f / 16.0f);
    float d = (lane < 16) ? (f - mu) : 0.0f;
    float ss = d * d;
    #pragma unroll
    for (int o = 16; o; o >>= 1) ss += __shfl_xor_sync(0xffffffffu, ss, o);
    float rstd = rsqrtf(ss * (1.0f / 16.0f) + LN_EPS);
    if (lane < 16) lns[warp][lane] = d * rstd * lng[lane] + lnb[lane];
    __syncwarp();

    #pragma unroll
    for (int t = 0; t < 2; t++) {
        int j = lane + 32 * t;
        float acc = 0.0f;
        #pragma unroll
        for (int i = 0; i < 16; i++) acc += lns[warp][i] * w1[i * 64 + j];
        g_hT[(size_t)j * MAXN + n] = silu_f(acc);
    }

    for (int t = lane; t < NJ; t += 32) {
        int p = t / 136, q = t % 136, u = 0;
        while (q >= 16 - u) { q -= 16 - u; u++; }
        int v = u + q;
        float val;
        if (p == 0) {
            val = PATH_COEFF * xs[warp][u] * xs[warp][v];
        } else {
            const float* a = &xs[warp][16 + u * 3];
            const float* b = &xs[warp][16 + v * 3];
            val = PATH_COEFF * CG110 * (a[0] * b[0] + a[1] * b[1] + a[2] * b[2]);
        }
        cs[warp * NJ + t] = val;
    }
    __syncthreads();

    for (int t = tid; t < NJC * 32; t += 512) {
        int l = t & 31;
        int jc = t >> 5;
        int ra = l >> 2;
        int j0 = jc * 16 + (l & 3) * 2;
        const float* c0 = cs + ra * NJ;
        const float* c8 = c0 + 8 * NJ;
        float4 f0, f1;
        f0.x = c0[j0];     f0.y = c0[j0 + 1]; f0.z = c8[j0];     f0.w = c8[j0 + 1];
        f1.x = c0[j0 + 8]; f1.y = c0[j0 + 9]; f1.z = c8[j0 + 8]; f1.w = c8[j0 + 9];
        size_t o = ((size_t)(mt * NJC + jc) * 32 + l) * 2;
        g_cf[o] = f0;
        g_cf[o + 1] = f1;
    }
}

// ---------------------------------------------------------------------------
// Kernel 3: HMMA contraction, fp16 1-term. Grid (N/128, 17), 256 threads,
// 2 CTA/SM. Warp tile 32 rows x 64 cols. (unchanged from R15)
// ---------------------------------------------------------------------------
__global__ __launch_bounds__(256, 2) void tp_kernel(int N) {
    __shared__ float h_sm[KC * 128];
    __shared__ uint2 sbuf[2][512];
    int tid = threadIdx.x;
    int warp = tid >> 5;
    int lane = tid & 31;
    int mblk = blockIdx.x;
    int base = mblk * 128;
    int split = blockIdx.y;
    int k0 = split * KC;

    for (int s = tid; s < KC * 128; s += 256) {
        int k = k0 + (s >> 7);
        float hv = 0.0f;
        if (k < 64)       hv = g_hT[(size_t)k * MAXN + base + (s & 127)];
        else if (k == 64) hv = 1.0f;
        h_sm[s] = hv;
    }
    {
        size_t o0 = (size_t)(k0 * NJC) * 512;
        sbuf[0][tid]       = g_bf[o0 + tid];
        sbuf[0][tid + 256] = g_bf[o0 + tid + 256];
    }
    __syncthreads();

    int mw = warp >> 1;
    int nh = warp & 1;
    int ra = lane >> 2;
    int qb = lane & 3;

    float acc[2][8][4];
    #pragma unroll
    for (int a = 0; a < 2; a++)
        #pragma unroll
        for (int b = 0; b < 8; b++)
            #pragma unroll
            for (int cdx = 0; cdx < 4; cdx++) acc[a][b][cdx] = 0.0f;

    const int T = NJC * KC;
    int t = 0;
    for (int jc = 0; jc < NJC; jc++) {
        float4 cf[2][2];
        #pragma unroll
        for (int mtl = 0; mtl < 2; mtl++) {
            int mt = mblk * 8 + mw * 2 + mtl;
            size_t o = ((size_t)(mt * NJC + jc) * 32 + lane) * 2;
            cf[mtl][0] = g_cf[o];
            cf[mtl][1] = g_cf[o + 1];
        }
        #pragma unroll
        for (int kk = 0; kk < KC; kk++, t++) {
            int cur = t & 1, nxt = cur ^ 1;
            bool hn = (t + 1 < T);
            uint2 p0, p1;
            if (hn) {
                int kn = kk + 1, jn = jc;
                if (kn == KC) { kn = 0; jn = jc + 1; }
                size_t off = (size_t)((k0 + kn) * NJC + jn) * 512;
                p0 = g_bf[off + tid];
                p1 = g_bf[off + tid + 256];
            }
            unsigned ah[2][4];
            #pragma unroll
            for (int mtl = 0; mtl < 2; mtl++) {
                int r = mw * 32 + mtl * 16 + ra;
                float h0 = h_sm[kk * 128 + r];
                float h1 = h_sm[kk * 128 + r + 8];
                ah[mtl][0] = cvt2h(h0 * cf[mtl][0].x, h0 * cf[mtl][0].y);
                ah[mtl][1] = cvt2h(h1 * cf[mtl][0].z, h1 * cf[mtl][0].w);
                ah[mtl][2] = cvt2h(h0 * cf[mtl][1].x, h0 * cf[mtl][1].y);
                ah[mtl][3] = cvt2h(h1 * cf[mtl][1].z, h1 * cf[mtl][1].w);
            }
            const uint2* bl = &sbuf[cur][nh * 256 + lane];
            #pragma unroll
            for (int wt = 0; wt < 8; wt++) {
                uint2 bb = bl[wt * 32];
                mma16816(acc[0][wt], ah[0], bb.x, bb.y);
                mma16816(acc[1][wt], ah[1], bb.x, bb.y);
            }
            if (hn) {
                sbuf[nxt][tid]       = p0;
                sbuf[nxt][tid + 256] = p1;
            }
            __syncthreads();
        }
    }

    #pragma unroll
    for (int mtl = 0; mtl < 2; mtl++) {
        int r0 = base + mw * 32 + mtl * 16 + ra;
        #pragma unroll
        for (int wt = 0; wt < 8; wt++) {
            int col = nh * 64 + wt * 8 + 2 * qb;
            float2* q0 = reinterpret_cast<float2*>(
                g_tp + ((size_t)split * N + r0) * 128 + col);
            float2* q1 = reinterpret_cast<float2*>(
                g_tp + ((size_t)split * N + r0 + 8) * 128 + col);
            *q0 = make_float2(acc[mtl][wt][0], acc[mtl][wt][1]);
            *q1 = make_float2(acc[mtl][wt][2], acc[mtl][wt][3]);
        }
    }
}

// ---------------------------------------------------------------------------
// Kernel 4: epilogue — sum 17 splits + LN(128), then y = LN @ om_w1 via HMMA,
// silu(y) @ om_w2 + b. 16 rows/block, 256 threads (8 warps, warp = 64 cols).
// ---------------------------------------------------------------------------
__global__ __launch_bounds__(256) void out_kernel(const float* __restrict__ lng,
                                                  const float* __restrict__ lnb,
                                                  const float* __restrict__ w2,
                                                  const float* __restrict__ bias2,
                                                  float* __restrict__ out, int N) {
    __shared__ float ln_sm[16][132];   // padded: kills LDS bank conflicts
    __shared__ float part_sm[16][8];
    int tid = threadIdx.x, lane = tid & 31, warp = tid >> 5;
    int rowbase = blockIdx.x * 16;

    // Phase A: 2 rows per warp — sum 17 splits + LayerNorm
    #pragma unroll
    for (int rr = 0; rr < 2; rr++) {
        int r = warp * 2 + rr;
        int g = rowbase + r;
        float v[4];
        #pragma unroll
        for (int t = 0; t < 4; t++) {
            int i = lane + 32 * t;
            float s = 0.0f;
            #pragma unroll
            for (int sp = 0; sp < KSPLIT; sp++)
                s += g_tp[((size_t)sp * N + g) * 128 + i];
            v[t] = s;
        }
        float s = v[0] + v[1] + v[2] + v[3];
        #pragma unroll
        for (int o = 16; o; o >>= 1) s += __shfl_xor_sync(0xffffffffu, s, o);
        float mu = s * (1.0f / 128.0f);
        float ss = 0.0f;
        #pragma unroll
        for (int t = 0; t < 4; t++) { float d = v[t] - mu; ss += d * d; }
        #pragma unroll
        for (int o = 16; o; o >>= 1) ss += __shfl_xor_sync(0xffffffffu, ss, o);
        float rstd = rsqrtf(ss * (1.0f / 128.0f) + LN_EPS);
        #pragma unroll
        for (int t = 0; t < 4; t++) {
            int i = lane + 32 * t;
            ln_sm[r][i] = (v[t] - mu) * rstd * lng[i] + lnb[i];
        }
    }
    __syncthreads();

    // Phase B: y(16 x 512) = ln @ om_w1 via HMMA; warp owns 64 cols.
    int ra = lane >> 2;
    int qb = lane & 3;
    float acc[8][4];
    #pragma unroll
    for (int b = 0; b < 8; b++)
        #pragma unroll
        for (int cdx = 0; cdx < 4; cdx++) acc[b][cdx] = 0.0f;

    #pragma unroll
    for (int ks = 0; ks < 8; ks++) {
        unsigned a[4];
        int k0 = ks * 16 + qb * 2;
        a[0] = cvt2h(ln_sm[ra][k0],         ln_sm[ra][k0 + 1]);
        a[1] = cvt2h(ln_sm[ra + 8][k0],     ln_sm[ra + 8][k0 + 1]);
        a[2] = cvt2h(ln_sm[ra][k0 + 8],     ln_sm[ra][k0 + 9]);
        a[3] = cvt2h(ln_sm[ra + 8][k0 + 8], ln_sm[ra + 8][k0 + 9]);
        const uint2* bp = g_w1f + ((size_t)ks * 64 + warp * 8) * 32 + lane;
        #pragma unroll
        for (int wt = 0; wt < 8; wt++) {
            uint2 bb = bp[wt * 32];
            mma16816(acc[wt], a, bb.x, bb.y);
        }
    }

    // Phase C: silu + dot with om_w2, reduce over qb then warps
    float s0 = 0.0f, s1 = 0.0f;
    const float2* w2v = reinterpret_cast<const float2*>(w2);
    #pragma unroll
    for (int wt = 0; wt < 8; wt++) {
        float2 wv = w2v[warp * 32 + wt * 4 + qb];
        s0 += silu_f(acc[wt][0]) * wv.x + silu_f(acc[wt][1]) * wv.y;
        s1 += silu_f(acc[wt][2]) * wv.x + silu_f(acc[wt][3]) * wv.y;
    }
    s0 += __shfl_xor_sync(0xffffffffu, s0, 1);
    s0 += __shfl_xor_sync(0xffffffffu, s0, 2);
    s1 += __shfl_xor_sync(0xffffffffu, s1, 1);
    s1 += __shfl_xor_sync(0xffffffffu, s1, 2);
    if (qb == 0) {
        part_sm[ra][warp]     = s0;
        part_sm[ra + 8][warp] = s1;
    }
    __syncthreads();

    if (tid < 16) {
        float s = 0.0f;
        #pragma unroll
        for (int w = 0; w < 8; w++) s += part_sm[tid][w];
        out[rowbase + tid] = s + bias2[0];
    }
}

// ---------------------------------------------------------------------------
extern "C" void kernel_launch(void* const* d_in, const int* in_sizes, int n_in,
                              void* d_out, int out_size) {
    const float* x        = (const float*)d_in[0];
    const float* we_ln_g  = (const float*)d_in[1];
    const float* we_ln_b  = (const float*)d_in[2];
    const float* we_w1    = (const float*)d_in[3];
    const float* we_w2    = (const float*)d_in[4];
    const float* we_b2    = (const float*)d_in[5];
    const float* om_ln_g  = (const float*)d_in[6];
    const float* om_ln_b  = (const float*)d_in[7];
    const float* om_w1    = (const float*)d_in[8];
    const float* om_w2    = (const float*)d_in[9];
    const float* om_b2    = (const float*)d_in[10];

    int N = in_sizes[0] / 64;
    if (N > MAXN) N = MAXN;

    bfrag_kernel<<<NKP * NJC, 256>>>(we_w2, we_b2);
    w1frag_kernel<<<(8 * 64 * 32 + 255) / 256, 256>>>(om_w1);
    prep_kernel<<<N / 16, 512>>>(x, we_ln_g, we_ln_b, we_w1, N);
    tp_kernel<<<dim3(N / 128, KSPLIT), 256>>>(N);
    out_kernel<<<N / 16, 256>>>(om_ln_g, om_ln_b, om_w2, om_b2,
                                (float*)d_out, N);
}